// round 1
// baseline (speedup 1.0000x reference)
#include <cuda_runtime.h>
#include <cuda_bf16.h>
#include <math.h>

#define N_TOK   4096
#define D_MODEL 1024
#define N_HEADS 16
#define HEAD_DIM 64

// Scratch (allocation-free rule: __device__ globals)
__device__ float g_q[N_TOK * D_MODEL];
__device__ float g_k[N_TOK * D_MODEL];
__device__ float g_v[N_TOK * D_MODEL];
__device__ float g_ctx[N_TOK * D_MODEL];

// ---------------------------------------------------------------------------
// GEMM: Y[m][n] = sum_k X[m][k] * W[n][k]  (+ bias[n] if bias != nullptr)
// Both X and W are K-major (row-major, K contiguous) -> A @ B^T shape.
// BM=BN=128, BK=16, 256 threads, 8x8 register tile per thread.
// ---------------------------------------------------------------------------
__global__ __launch_bounds__(256) void gemm_xwt_kernel(
    const float* __restrict__ X, const float* __restrict__ W,
    const float* __restrict__ bias, float* __restrict__ Y,
    int M, int N, int K)
{
    __shared__ float As[16][129];
    __shared__ float Bs[16][129];

    const int tid = threadIdx.x;
    const int m0 = blockIdx.y * 128;
    const int n0 = blockIdx.x * 128;
    const int ty = tid >> 4;          // 0..15
    const int tx = tid & 15;          // 0..15

    float acc[8][8];
#pragma unroll
    for (int i = 0; i < 8; i++)
#pragma unroll
        for (int j = 0; j < 8; j++) acc[i][j] = 0.f;

    const int lm = tid >> 2;          // 0..63
    const int lk = (tid & 3) << 2;    // 0,4,8,12

    for (int k0 = 0; k0 < K; k0 += 16) {
#pragma unroll
        for (int half = 0; half < 2; half++) {
            int m = lm + half * 64;
            float4 xa = *(const float4*)(X + (size_t)(m0 + m) * K + k0 + lk);
            As[lk + 0][m] = xa.x; As[lk + 1][m] = xa.y;
            As[lk + 2][m] = xa.z; As[lk + 3][m] = xa.w;
            float4 xb = *(const float4*)(W + (size_t)(n0 + m) * K + k0 + lk);
            Bs[lk + 0][m] = xb.x; Bs[lk + 1][m] = xb.y;
            Bs[lk + 2][m] = xb.z; Bs[lk + 3][m] = xb.w;
        }
        __syncthreads();

#pragma unroll
        for (int kk = 0; kk < 16; kk++) {
            float a[8], b[8];
#pragma unroll
            for (int i = 0; i < 8; i++) a[i] = As[kk][ty + 16 * i];
#pragma unroll
            for (int j = 0; j < 8; j++) b[j] = Bs[kk][tx + 16 * j];
#pragma unroll
            for (int i = 0; i < 8; i++)
#pragma unroll
                for (int j = 0; j < 8; j++)
                    acc[i][j] = fmaf(a[i], b[j], acc[i][j]);
        }
        __syncthreads();
    }

#pragma unroll
    for (int i = 0; i < 8; i++) {
        int m = m0 + ty + 16 * i;
#pragma unroll
        for (int j = 0; j < 8; j++) {
            int n = n0 + tx + 16 * j;
            float v = acc[i][j];
            if (bias) v += bias[n];
            Y[(size_t)m * N + n] = v;
        }
    }
}

// ---------------------------------------------------------------------------
// Flash attention (causal, fp32). One CTA = (64-query block, head).
// 256 threads: rows r_i = ty+16i, cols/dims c_j = tx+16j (4x4 per thread).
// Streams 64-key tiles; online softmax; row stats via 16-lane shfl reduce.
// ---------------------------------------------------------------------------
__global__ __launch_bounds__(256) void attn_kernel()
{
    extern __shared__ float smem[];
    float (*Qs)[65] = (float(*)[65])(smem);
    float (*Ks)[65] = (float(*)[65])(smem + 64 * 65);
    float (*Vs)[65] = (float(*)[65])(smem + 2 * 64 * 65);
    float (*Ss)[65] = (float(*)[65])(smem + 3 * 64 * 65);

    const int qb  = blockIdx.x;       // 0..63
    const int h   = blockIdx.y;       // 0..15
    const int tid = threadIdx.x;
    const int ty  = tid >> 4;         // 0..15
    const int tx  = tid & 15;         // 0..15

    // Load Q tile (64 rows x 64 dims)
    {
        int row = tid >> 2;
        int d0  = (tid & 3) << 4;
        const float* src = g_q + (size_t)(qb * 64 + row) * D_MODEL + h * HEAD_DIM + d0;
#pragma unroll
        for (int v = 0; v < 4; v++) {
            float4 t = *(const float4*)(src + v * 4);
            Qs[row][d0 + v * 4 + 0] = t.x; Qs[row][d0 + v * 4 + 1] = t.y;
            Qs[row][d0 + v * 4 + 2] = t.z; Qs[row][d0 + v * 4 + 3] = t.w;
        }
    }

    float Oacc[4][4];
    float l[4], mprev[4];
#pragma unroll
    for (int i = 0; i < 4; i++) {
        l[i] = 0.f; mprev[i] = -INFINITY;
#pragma unroll
        for (int j = 0; j < 4; j++) Oacc[i][j] = 0.f;
    }

    for (int kb = 0; kb <= qb; kb++) {
        __syncthreads();  // prior-iter Ss/Vs reads done; Q store visible after next sync

        // Load K,V tiles
        {
            int row = tid >> 2;
            int d0  = (tid & 3) << 4;
            const float* ksrc = g_k + (size_t)(kb * 64 + row) * D_MODEL + h * HEAD_DIM + d0;
            const float* vsrc = g_v + (size_t)(kb * 64 + row) * D_MODEL + h * HEAD_DIM + d0;
#pragma unroll
            for (int v = 0; v < 4; v++) {
                float4 t = *(const float4*)(ksrc + v * 4);
                Ks[row][d0 + v * 4 + 0] = t.x; Ks[row][d0 + v * 4 + 1] = t.y;
                Ks[row][d0 + v * 4 + 2] = t.z; Ks[row][d0 + v * 4 + 3] = t.w;
                float4 u = *(const float4*)(vsrc + v * 4);
                Vs[row][d0 + v * 4 + 0] = u.x; Vs[row][d0 + v * 4 + 1] = u.y;
                Vs[row][d0 + v * 4 + 2] = u.z; Vs[row][d0 + v * 4 + 3] = u.w;
            }
        }
        __syncthreads();

        // S = (Q K^T) / 8, causal mask on diagonal tile
        float s[4][4];
#pragma unroll
        for (int i = 0; i < 4; i++)
#pragma unroll
            for (int j = 0; j < 4; j++) s[i][j] = 0.f;

#pragma unroll 4
        for (int d = 0; d < 64; d++) {
            float a[4], b[4];
#pragma unroll
            for (int i = 0; i < 4; i++) a[i] = Qs[ty + 16 * i][d];
#pragma unroll
            for (int j = 0; j < 4; j++) b[j] = Ks[tx + 16 * j][d];
#pragma unroll
            for (int i = 0; i < 4; i++)
#pragma unroll
                for (int j = 0; j < 4; j++)
                    s[i][j] = fmaf(a[i], b[j], s[i][j]);
        }

        const bool diag = (kb == qb);
#pragma unroll
        for (int i = 0; i < 4; i++) {
            int rg = qb * 64 + ty + 16 * i;
#pragma unroll
            for (int j = 0; j < 4; j++) {
                int cg = kb * 64 + tx + 16 * j;
                s[i][j] = (diag && cg > rg) ? -INFINITY : s[i][j] * 0.125f;
            }
        }

        // Online softmax per row
        float alpha[4];
#pragma unroll
        for (int i = 0; i < 4; i++) {
            float m = fmaxf(fmaxf(s[i][0], s[i][1]), fmaxf(s[i][2], s[i][3]));
#pragma unroll
            for (int w = 1; w < 16; w <<= 1)
                m = fmaxf(m, __shfl_xor_sync(0xffffffffu, m, w));
            float mnew = fmaxf(mprev[i], m);
            float ls = 0.f;
#pragma unroll
            for (int j = 0; j < 4; j++) { s[i][j] = __expf(s[i][j] - mnew); ls += s[i][j]; }
#pragma unroll
            for (int w = 1; w < 16; w <<= 1)
                ls += __shfl_xor_sync(0xffffffffu, ls, w);
            alpha[i] = __expf(mprev[i] - mnew);
            l[i] = l[i] * alpha[i] + ls;
            mprev[i] = mnew;
        }

        // Stage P
#pragma unroll
        for (int i = 0; i < 4; i++)
#pragma unroll
            for (int j = 0; j < 4; j++)
                Ss[ty + 16 * i][tx + 16 * j] = s[i][j];
        __syncthreads();

        // O = O*alpha + P @ V
#pragma unroll
        for (int i = 0; i < 4; i++)
#pragma unroll
            for (int j = 0; j < 4; j++)
                Oacc[i][j] *= alpha[i];

#pragma unroll 4
        for (int c = 0; c < 64; c++) {
            float p[4], b[4];
#pragma unroll
            for (int i = 0; i < 4; i++) p[i] = Ss[ty + 16 * i][c];
#pragma unroll
            for (int j = 0; j < 4; j++) b[j] = Vs[c][tx + 16 * j];
#pragma unroll
            for (int i = 0; i < 4; i++)
#pragma unroll
                for (int j = 0; j < 4; j++)
                    Oacc[i][j] = fmaf(p[i], b[j], Oacc[i][j]);
        }
    }

    // Normalize and write ctx (heads back in [n, D] layout)
#pragma unroll
    for (int i = 0; i < 4; i++) {
        float inv = 1.f / l[i];
        int row = qb * 64 + ty + 16 * i;
#pragma unroll
        for (int j = 0; j < 4; j++)
            g_ctx[(size_t)row * D_MODEL + h * HEAD_DIM + tx + 16 * j] = Oacc[i][j] * inv;
    }
}

// ---------------------------------------------------------------------------
extern "C" void kernel_launch(void* const* d_in, const int* in_sizes, int n_in,
                              void* d_out, int out_size)
{
    const float* x  = (const float*)d_in[0];
    const float* Wq = (const float*)d_in[1];
    const float* Wk = (const float*)d_in[2];
    const float* Wv = (const float*)d_in[3];
    const float* Wo = (const float*)d_in[4];
    const float* bo = (const float*)d_in[5];
    float* out = (float*)d_out;

    float *q, *k, *v, *ctx;
    cudaGetSymbolAddress((void**)&q,   g_q);
    cudaGetSymbolAddress((void**)&k,   g_k);
    cudaGetSymbolAddress((void**)&v,   g_v);
    cudaGetSymbolAddress((void**)&ctx, g_ctx);

    dim3 blk(256);
    dim3 grid_proj(D_MODEL / 128, N_TOK / 128);  // (8, 32)

    gemm_xwt_kernel<<<grid_proj, blk>>>(x, Wq, nullptr, q, N_TOK, D_MODEL, D_MODEL);
    gemm_xwt_kernel<<<grid_proj, blk>>>(x, Wk, nullptr, k, N_TOK, D_MODEL, D_MODEL);
    gemm_xwt_kernel<<<grid_proj, blk>>>(x, Wv, nullptr, v, N_TOK, D_MODEL, D_MODEL);

    const int attn_smem = 4 * 64 * 65 * (int)sizeof(float);  // 66560 B
    cudaFuncSetAttribute(attn_kernel, cudaFuncAttributeMaxDynamicSharedMemorySize, attn_smem);
    attn_kernel<<<dim3(N_TOK / 64, N_HEADS), blk, attn_smem>>>();

    gemm_xwt_kernel<<<grid_proj, blk>>>(ctx, Wo, bo, out, N_TOK, D_MODEL, D_MODEL);
}

// round 3
// speedup vs baseline: 1.6774x; 1.6774x over previous
#include <cuda_runtime.h>
#include <cuda_bf16.h>
#include <math.h>
#include <stdint.h>

#define N_TOK   4096
#define D_MODEL 1024
#define N_HEADS 16
#define HEAD_DIM 64

// ---------------- device scratch (allocation-free rule) ----------------
__device__ float g_q[N_TOK * D_MODEL];
__device__ float g_k[N_TOK * D_MODEL];
__device__ float g_v[N_TOK * D_MODEL];
__device__ float g_ctx[N_TOK * D_MODEL];

__device__ __nv_bfloat16 g_xhi[N_TOK * D_MODEL];
__device__ __nv_bfloat16 g_xlo[N_TOK * D_MODEL];
__device__ __nv_bfloat16 g_chi[N_TOK * D_MODEL];
__device__ __nv_bfloat16 g_clo[N_TOK * D_MODEL];
__device__ __nv_bfloat16 g_whi[4][D_MODEL * D_MODEL];
__device__ __nv_bfloat16 g_wlo[4][D_MODEL * D_MODEL];

// ---------------- PTX helpers (sm_80-compatible only; no tcgen05!) ------
__device__ __forceinline__ uint32_t smem_u32(const void* p) {
    uint32_t a;
    asm("{ .reg .u64 t; cvta.to.shared.u64 t, %1; cvt.u32.u64 %0, t; }" : "=r"(a) : "l"(p));
    return a;
}

#define CP16(s, g) \
    asm volatile("cp.async.cg.shared.global [%0], [%1], 16;" :: "r"(s), "l"(g))
#define CP_COMMIT() asm volatile("cp.async.commit_group;" ::: "memory")
#define CP_WAIT(n)  asm volatile("cp.async.wait_group %0;" :: "n"(n) : "memory")

#define LDMX4(r, addr) \
    asm volatile("ldmatrix.sync.aligned.m8n8.x4.shared.b16 {%0,%1,%2,%3}, [%4];" \
        : "=r"((r)[0]), "=r"((r)[1]), "=r"((r)[2]), "=r"((r)[3]) : "r"(addr))

#define MMA_BF16(d, a, b0, b1) \
    asm volatile("mma.sync.aligned.m16n8k16.row.col.f32.bf16.bf16.f32 " \
        "{%0,%1,%2,%3}, {%4,%5,%6,%7}, {%8,%9}, {%0,%1,%2,%3};" \
        : "+f"((d)[0]), "+f"((d)[1]), "+f"((d)[2]), "+f"((d)[3]) \
        : "r"((a)[0]), "r"((a)[1]), "r"((a)[2]), "r"((a)[3]), "r"(b0), "r"(b1))

// ---------------------------------------------------------------------------
// split fp32 -> bf16 hi + bf16 lo (residual)
// ---------------------------------------------------------------------------
__global__ __launch_bounds__(256) void split_kernel(
    const float* __restrict__ src, __nv_bfloat16* __restrict__ hi,
    __nv_bfloat16* __restrict__ lo, int n)
{
    int i = (blockIdx.x * 256 + threadIdx.x) * 4;
    if (i >= n) return;
    float4 v = *(const float4*)(src + i);
    __nv_bfloat16 h0 = __float2bfloat16(v.x);
    __nv_bfloat16 h1 = __float2bfloat16(v.y);
    __nv_bfloat16 h2 = __float2bfloat16(v.z);
    __nv_bfloat16 h3 = __float2bfloat16(v.w);
    __nv_bfloat16 l0 = __float2bfloat16(v.x - __bfloat162float(h0));
    __nv_bfloat16 l1 = __float2bfloat16(v.y - __bfloat162float(h1));
    __nv_bfloat16 l2 = __float2bfloat16(v.z - __bfloat162float(h2));
    __nv_bfloat16 l3 = __float2bfloat16(v.w - __bfloat162float(h3));
    __nv_bfloat162* ph = (__nv_bfloat162*)(hi + i);
    __nv_bfloat162* pl = (__nv_bfloat162*)(lo + i);
    ph[0] = __nv_bfloat162(h0, h1); ph[1] = __nv_bfloat162(h2, h3);
    pl[0] = __nv_bfloat162(l0, l1); pl[1] = __nv_bfloat162(l2, l3);
}

// ---------------------------------------------------------------------------
// HMMA split-bf16 GEMM: C[m][n] = sum_k A[m][k]*B[n][k] (+bias[n])
// fp32 = hi + lo; compute hh + hl + lh (drop lo*lo).
// CTA 128x128, BK=32, 256 threads (8 warps, each 32m x 64n), double-buffered
// cp.async, XOR-swizzled smem for conflict-free ldmatrix.
// Smem layout per stage (32KB): Ahi[128][32] | Alo | Bhi[128][32] | Blo,
// each row 64B, chunk swizzle: phys_chunk = chunk ^ ((row>>1)&3).
// ---------------------------------------------------------------------------
#define GSTAGE 32768
#define GSMEM  (2 * GSTAGE)
#define NCHUNK 32

__device__ __forceinline__ void load_chunk(
    uint32_t sbase, int tid, int m0, int n0, int kc,
    const __nv_bfloat16* __restrict__ Ahi, const __nv_bfloat16* __restrict__ Alo,
    const __nv_bfloat16* __restrict__ Bhi, const __nv_bfloat16* __restrict__ Blo)
{
    const int row = tid >> 2;
    const int chunk = tid & 3;
    const int kcol = kc * 32 + chunk * 8;
#pragma unroll
    for (int u = 0; u < 2; u++) {
        const int r = row + u * 64;
        const uint32_t so = (uint32_t)(r * 64 + ((chunk ^ ((r >> 1) & 3)) << 4));
        CP16(sbase + so,         (const char*)(Ahi + (size_t)(m0 + r) * 1024 + kcol));
        CP16(sbase + 8192 + so,  (const char*)(Alo + (size_t)(m0 + r) * 1024 + kcol));
        CP16(sbase + 16384 + so, (const char*)(Bhi + (size_t)(n0 + r) * 1024 + kcol));
        CP16(sbase + 24576 + so, (const char*)(Blo + (size_t)(n0 + r) * 1024 + kcol));
    }
}

__global__ __launch_bounds__(256) void gemm_mma_kernel(
    const __nv_bfloat16* __restrict__ Ahi, const __nv_bfloat16* __restrict__ Alo,
    const __nv_bfloat16* __restrict__ Bhi, const __nv_bfloat16* __restrict__ Blo,
    const float* __restrict__ bias, float* __restrict__ C)
{
    extern __shared__ __align__(128) char smem[];
    const uint32_t sb = smem_u32(smem);
    const int tid = threadIdx.x;
    const int wid = tid >> 5;
    const int lid = tid & 31;
    const int n0 = blockIdx.x * 128;
    const int m0 = blockIdx.y * 128;
    const int warp_m = (wid >> 1) * 32;
    const int warp_n = (wid & 1) * 64;

    float acc[2][8][4];
#pragma unroll
    for (int a = 0; a < 2; a++)
#pragma unroll
        for (int b = 0; b < 8; b++)
#pragma unroll
            for (int c = 0; c < 4; c++) acc[a][b][c] = 0.f;

    load_chunk(sb, tid, m0, n0, 0, Ahi, Alo, Bhi, Blo);
    CP_COMMIT();

    const int sub = lid >> 3;
    const int r8  = lid & 7;

    for (int kc = 0; kc < NCHUNK; kc++) {
        const uint32_t cur = sb + (uint32_t)(kc & 1) * GSTAGE;
        if (kc + 1 < NCHUNK) {
            load_chunk(sb + (uint32_t)((kc + 1) & 1) * GSTAGE, tid, m0, n0, kc + 1,
                       Ahi, Alo, Bhi, Blo);
            CP_COMMIT();
            CP_WAIT(1);
        } else {
            CP_WAIT(0);
        }
        __syncthreads();

#pragma unroll
        for (int ks = 0; ks < 2; ks++) {
            const int kchunk = ks * 2 + (sub >> 1);
            uint32_t ahi[2][4], alo[2][4], bfr[4][4];
            uint32_t bad[4];
#pragma unroll
            for (int mt = 0; mt < 2; mt++) {
                const int mr = warp_m + mt * 16 + ((sub & 1) << 3) + r8;
                const uint32_t ad = cur + (uint32_t)(mr * 64 + ((kchunk ^ ((mr >> 1) & 3)) << 4));
                LDMX4(ahi[mt], ad);
                LDMX4(alo[mt], ad + 8192);
            }
#pragma unroll
            for (int nt = 0; nt < 4; nt++) {
                const int nr = warp_n + nt * 16 + ((sub & 1) << 3) + r8;
                bad[nt] = cur + 16384 + (uint32_t)(nr * 64 + ((kchunk ^ ((nr >> 1) & 3)) << 4));
                LDMX4(bfr[nt], bad[nt]);
            }
            // hh + lh (both use Bhi)
#pragma unroll
            for (int mt = 0; mt < 2; mt++)
#pragma unroll
                for (int nt = 0; nt < 4; nt++) {
                    MMA_BF16(acc[mt][2 * nt + 0], ahi[mt], bfr[nt][0], bfr[nt][2]);
                    MMA_BF16(acc[mt][2 * nt + 1], ahi[mt], bfr[nt][1], bfr[nt][3]);
                    MMA_BF16(acc[mt][2 * nt + 0], alo[mt], bfr[nt][0], bfr[nt][2]);
                    MMA_BF16(acc[mt][2 * nt + 1], alo[mt], bfr[nt][1], bfr[nt][3]);
                }
            // hl (Ahi x Blo)
#pragma unroll
            for (int nt = 0; nt < 4; nt++)
                LDMX4(bfr[nt], bad[nt] + 8192);
#pragma unroll
            for (int mt = 0; mt < 2; mt++)
#pragma unroll
                for (int nt = 0; nt < 4; nt++) {
                    MMA_BF16(acc[mt][2 * nt + 0], ahi[mt], bfr[nt][0], bfr[nt][2]);
                    MMA_BF16(acc[mt][2 * nt + 1], ahi[mt], bfr[nt][1], bfr[nt][3]);
                }
        }
        __syncthreads();
    }

    // epilogue: c0,c1 at (m = l>>2, n = 2*(l&3)); c2,c3 at m+8
#pragma unroll
    for (int mt = 0; mt < 2; mt++) {
        const int mrow = m0 + warp_m + mt * 16 + (lid >> 2);
#pragma unroll
        for (int nt = 0; nt < 8; nt++) {
            const int ncol = n0 + warp_n + nt * 8 + 2 * (lid & 3);
            float b0 = 0.f, b1 = 0.f;
            if (bias) { b0 = bias[ncol]; b1 = bias[ncol + 1]; }
            float2 v0 = make_float2(acc[mt][nt][0] + b0, acc[mt][nt][1] + b1);
            float2 v1 = make_float2(acc[mt][nt][2] + b0, acc[mt][nt][3] + b1);
            *(float2*)(C + (size_t)mrow * 1024 + ncol)       = v0;
            *(float2*)(C + (size_t)(mrow + 8) * 1024 + ncol) = v1;
        }
    }
}

// ---------------------------------------------------------------------------
// Flash attention (causal, fp32), vectorized LDS.128 + swizzled K tile.
// One CTA = (64-query block, head). 256 threads.
// ---------------------------------------------------------------------------
__global__ __launch_bounds__(256) void attn_kernel()
{
    extern __shared__ __align__(16) float sm[];
    float* Qs = sm;             // [64][64]
    float* Ks = sm + 64 * 64;   // [64][64], float4-chunk XOR swizzle
    float* Vs = sm + 2 * 64 * 64;
    float* Ss = sm + 3 * 64 * 64;

    const int qb  = gridDim.x - 1 - blockIdx.x;  // long CTAs first
    const int h   = blockIdx.y;
    const int tid = threadIdx.x;
    const int ty  = tid >> 4;
    const int tx  = tid & 15;
    const int sw  = tx & 7;

    {
        const int row = tid >> 2;
        const int d0  = (tid & 3) << 4;
        const float* src = g_q + (size_t)(qb * 64 + row) * D_MODEL + h * HEAD_DIM + d0;
#pragma unroll
        for (int v2 = 0; v2 < 4; v2++)
            *(float4*)(Qs + row * 64 + d0 + v2 * 4) = *(const float4*)(src + v2 * 4);
    }

    float O[4][4];
    float l[4], mprev[4];
#pragma unroll
    for (int i = 0; i < 4; i++) {
        l[i] = 0.f; mprev[i] = -INFINITY;
#pragma unroll
        for (int j = 0; j < 4; j++) O[i][j] = 0.f;
    }

    for (int kb = 0; kb <= qb; kb++) {
        __syncthreads();
        {
            const int row = tid >> 2;
            const int d0  = (tid & 3) << 4;
            const int rsw = (row >> 2) & 7;
            const float* ksrc = g_k + (size_t)(kb * 64 + row) * D_MODEL + h * HEAD_DIM + d0;
            const float* vsrc = g_v + (size_t)(kb * 64 + row) * D_MODEL + h * HEAD_DIM + d0;
#pragma unroll
            for (int v2 = 0; v2 < 4; v2++) {
                float4 t = *(const float4*)(ksrc + v2 * 4);
                int q = (d0 >> 2) + v2;
                *(float4*)(Ks + row * 64 + ((q ^ rsw) << 2)) = t;
                *(float4*)(Vs + row * 64 + d0 + v2 * 4) = *(const float4*)(vsrc + v2 * 4);
            }
        }
        __syncthreads();

        float s[4][4];
#pragma unroll
        for (int i = 0; i < 4; i++)
#pragma unroll
            for (int j = 0; j < 4; j++) s[i][j] = 0.f;

#pragma unroll 4
        for (int q = 0; q < 16; q++) {
            float4 a[4], b[4];
#pragma unroll
            for (int i = 0; i < 4; i++) a[i] = *(float4*)(Qs + (4 * ty + i) * 64 + q * 4);
#pragma unroll
            for (int j = 0; j < 4; j++) b[j] = *(float4*)(Ks + (4 * tx + j) * 64 + ((q ^ sw) << 2));
#pragma unroll
            for (int i = 0; i < 4; i++)
#pragma unroll
                for (int j = 0; j < 4; j++) {
                    s[i][j] = fmaf(a[i].x, b[j].x, s[i][j]);
                    s[i][j] = fmaf(a[i].y, b[j].y, s[i][j]);
                    s[i][j] = fmaf(a[i].z, b[j].z, s[i][j]);
                    s[i][j] = fmaf(a[i].w, b[j].w, s[i][j]);
                }
        }

        const bool diag = (kb == qb);
#pragma unroll
        for (int i = 0; i < 4; i++) {
            int rg = qb * 64 + 4 * ty + i;
#pragma unroll
            for (int j = 0; j < 4; j++) {
                int cg = kb * 64 + 4 * tx + j;
                s[i][j] = (diag && cg > rg) ? -INFINITY : s[i][j] * 0.125f;
            }
        }

        float alpha[4];
#pragma unroll
        for (int i = 0; i < 4; i++) {
            float m = fmaxf(fmaxf(s[i][0], s[i][1]), fmaxf(s[i][2], s[i][3]));
#pragma unroll
            for (int w = 1; w < 16; w <<= 1)
                m = fmaxf(m, __shfl_xor_sync(0xffffffffu, m, w));
            float mnew = fmaxf(mprev[i], m);
            float ls = 0.f;
#pragma unroll
            for (int j = 0; j < 4; j++) { s[i][j] = __expf(s[i][j] - mnew); ls += s[i][j]; }
#pragma unroll
            for (int w = 1; w < 16; w <<= 1)
                ls += __shfl_xor_sync(0xffffffffu, ls, w);
            alpha[i] = __expf(mprev[i] - mnew);
            l[i] = l[i] * alpha[i] + ls;
            mprev[i] = mnew;
        }

#pragma unroll
        for (int i = 0; i < 4; i++)
            *(float4*)(Ss + (4 * ty + i) * 64 + 4 * tx) =
                make_float4(s[i][0], s[i][1], s[i][2], s[i][3]);
        __syncthreads();

#pragma unroll
        for (int i = 0; i < 4; i++)
#pragma unroll
            for (int j = 0; j < 4; j++) O[i][j] *= alpha[i];

#pragma unroll 4
        for (int cq = 0; cq < 16; cq++) {
            float4 p[4];
#pragma unroll
            for (int i = 0; i < 4; i++) p[i] = *(float4*)(Ss + (4 * ty + i) * 64 + cq * 4);
            float pa[4][4];
#pragma unroll
            for (int i = 0; i < 4; i++) {
                pa[i][0] = p[i].x; pa[i][1] = p[i].y; pa[i][2] = p[i].z; pa[i][3] = p[i].w;
            }
#pragma unroll
            for (int cc = 0; cc < 4; cc++) {
                float4 v = *(float4*)(Vs + (cq * 4 + cc) * 64 + 4 * tx);
#pragma unroll
                for (int i = 0; i < 4; i++) {
                    O[i][0] = fmaf(pa[i][cc], v.x, O[i][0]);
                    O[i][1] = fmaf(pa[i][cc], v.y, O[i][1]);
                    O[i][2] = fmaf(pa[i][cc], v.z, O[i][2]);
                    O[i][3] = fmaf(pa[i][cc], v.w, O[i][3]);
                }
            }
        }
    }

#pragma unroll
    for (int i = 0; i < 4; i++) {
        float inv = 1.f / l[i];
        int row = qb * 64 + 4 * ty + i;
        float4 o = make_float4(O[i][0] * inv, O[i][1] * inv, O[i][2] * inv, O[i][3] * inv);
        *(float4*)(g_ctx + (size_t)row * D_MODEL + h * HEAD_DIM + 4 * tx) = o;
    }
}

// ---------------------------------------------------------------------------
extern "C" void kernel_launch(void* const* d_in, const int* in_sizes, int n_in,
                              void* d_out, int out_size)
{
    const float* x  = (const float*)d_in[0];
    const float* Wq = (const float*)d_in[1];
    const float* Wk = (const float*)d_in[2];
    const float* Wv = (const float*)d_in[3];
    const float* Wo = (const float*)d_in[4];
    const float* bo = (const float*)d_in[5];
    float* out = (float*)d_out;

    float *q, *k, *v, *ctx;
    __nv_bfloat16 *xhi, *xlo, *chi, *clo, *whi, *wlo;
    cudaGetSymbolAddress((void**)&q,   g_q);
    cudaGetSymbolAddress((void**)&k,   g_k);
    cudaGetSymbolAddress((void**)&v,   g_v);
    cudaGetSymbolAddress((void**)&ctx, g_ctx);
    cudaGetSymbolAddress((void**)&xhi, g_xhi);
    cudaGetSymbolAddress((void**)&xlo, g_xlo);
    cudaGetSymbolAddress((void**)&chi, g_chi);
    cudaGetSymbolAddress((void**)&clo, g_clo);
    cudaGetSymbolAddress((void**)&whi, g_whi);
    cudaGetSymbolAddress((void**)&wlo, g_wlo);

    const int NX = N_TOK * D_MODEL;       // 4M
    const int NW = D_MODEL * D_MODEL;     // 1M
    const float* Ws[4] = {Wq, Wk, Wv, Wo};

    split_kernel<<<NX / 1024, 256>>>(x, xhi, xlo, NX);
    for (int i = 0; i < 4; i++)
        split_kernel<<<NW / 1024, 256>>>(Ws[i], whi + (size_t)i * NW, wlo + (size_t)i * NW, NW);

    cudaFuncSetAttribute(gemm_mma_kernel, cudaFuncAttributeMaxDynamicSharedMemorySize, GSMEM);
    dim3 gg(D_MODEL / 128, N_TOK / 128);  // (8, 32)

    gemm_mma_kernel<<<gg, 256, GSMEM>>>(xhi, xlo, whi + 0 * (size_t)NW, wlo + 0 * (size_t)NW, nullptr, q);
    gemm_mma_kernel<<<gg, 256, GSMEM>>>(xhi, xlo, whi + 1 * (size_t)NW, wlo + 1 * (size_t)NW, nullptr, k);
    gemm_mma_kernel<<<gg, 256, GSMEM>>>(xhi, xlo, whi + 2 * (size_t)NW, wlo + 2 * (size_t)NW, nullptr, v);

    const int attn_smem = 4 * 64 * 64 * (int)sizeof(float);  // 65536
    cudaFuncSetAttribute(attn_kernel, cudaFuncAttributeMaxDynamicSharedMemorySize, attn_smem);
    attn_kernel<<<dim3(N_TOK / 64, N_HEADS), 256, attn_smem>>>();

    split_kernel<<<NX / 1024, 256>>>(ctx, chi, clo, NX);
    gemm_mma_kernel<<<gg, 256, GSMEM>>>(chi, clo, whi + 3 * (size_t)NW, wlo + 3 * (size_t)NW, bo, out);
}

// round 4
// speedup vs baseline: 3.8134x; 2.2734x over previous
#include <cuda_runtime.h>
#include <cuda_bf16.h>
#include <math.h>
#include <stdint.h>

#define N_TOK   4096
#define D_MODEL 1024
#define N_HEADS 16
#define HEAD_DIM 64

// ---------------- device scratch (allocation-free rule) ----------------
__device__ __nv_bfloat16 g_xhi[N_TOK * D_MODEL];
__device__ __nv_bfloat16 g_xlo[N_TOK * D_MODEL];
__device__ __nv_bfloat16 g_whi[4][D_MODEL * D_MODEL];
__device__ __nv_bfloat16 g_wlo[4][D_MODEL * D_MODEL];
__device__ __nv_bfloat16 g_qhi[N_TOK * D_MODEL];
__device__ __nv_bfloat16 g_qlo[N_TOK * D_MODEL];
__device__ __nv_bfloat16 g_khi[N_TOK * D_MODEL];
__device__ __nv_bfloat16 g_klo[N_TOK * D_MODEL];
__device__ __nv_bfloat16 g_vhi[N_TOK * D_MODEL];
__device__ __nv_bfloat16 g_vlo[N_TOK * D_MODEL];
__device__ __nv_bfloat16 g_chi[N_TOK * D_MODEL];
__device__ __nv_bfloat16 g_clo[N_TOK * D_MODEL];

// ---------------- PTX helpers (sm_80-compatible; NO tcgen05) ------------
__device__ __forceinline__ uint32_t smem_u32(const void* p) {
    uint32_t a;
    asm("{ .reg .u64 t; cvta.to.shared.u64 t, %1; cvt.u32.u64 %0, t; }" : "=r"(a) : "l"(p));
    return a;
}

#define CP16(s, g) \
    asm volatile("cp.async.cg.shared.global [%0], [%1], 16;" :: "r"(s), "l"(g))
#define CP_COMMIT() asm volatile("cp.async.commit_group;" ::: "memory")
#define CP_WAIT(n)  asm volatile("cp.async.wait_group %0;" :: "n"(n) : "memory")

#define LDMX4(r, addr) \
    asm volatile("ldmatrix.sync.aligned.m8n8.x4.shared.b16 {%0,%1,%2,%3}, [%4];" \
        : "=r"((r)[0]), "=r"((r)[1]), "=r"((r)[2]), "=r"((r)[3]) : "r"(addr))

#define LDMX4T(r, addr) \
    asm volatile("ldmatrix.sync.aligned.m8n8.x4.trans.shared.b16 {%0,%1,%2,%3}, [%4];" \
        : "=r"((r)[0]), "=r"((r)[1]), "=r"((r)[2]), "=r"((r)[3]) : "r"(addr))

#define MMA_BF16(d, a, b0, b1) \
    asm volatile("mma.sync.aligned.m16n8k16.row.col.f32.bf16.bf16.f32 " \
        "{%0,%1,%2,%3}, {%4,%5,%6,%7}, {%8,%9}, {%0,%1,%2,%3};" \
        : "+f"((d)[0]), "+f"((d)[1]), "+f"((d)[2]), "+f"((d)[3]) \
        : "r"((a)[0]), "r"((a)[1]), "r"((a)[2]), "r"((a)[3]), "r"(b0), "r"(b1))

// pack two fp32 -> bf16x2 (lo = a, hi = b)
__device__ __forceinline__ uint32_t pack_bf2(float a, float b) {
    uint32_t r;
    asm("cvt.rn.bf16x2.f32 %0, %1, %2;" : "=r"(r) : "f"(b), "f"(a));
    return r;
}
__device__ __forceinline__ float bfres(float x) {
    return x - __bfloat162float(__float2bfloat16(x));
}

// ---------------------------------------------------------------------------
// split fp32 -> bf16 hi + bf16 lo (residual)
// ---------------------------------------------------------------------------
__global__ __launch_bounds__(256) void split_kernel(
    const float* __restrict__ src, __nv_bfloat16* __restrict__ hi,
    __nv_bfloat16* __restrict__ lo, int n)
{
    int i = (blockIdx.x * 256 + threadIdx.x) * 4;
    if (i >= n) return;
    float4 v = *(const float4*)(src + i);
    uint32_t h0 = pack_bf2(v.x, v.y), h1 = pack_bf2(v.z, v.w);
    uint32_t l0 = pack_bf2(bfres(v.x), bfres(v.y));
    uint32_t l1 = pack_bf2(bfres(v.z), bfres(v.w));
    uint32_t* ph = (uint32_t*)(hi + i);
    uint32_t* pl = (uint32_t*)(lo + i);
    ph[0] = h0; ph[1] = h1;
    pl[0] = l0; pl[1] = l1;
}

// ---------------------------------------------------------------------------
// HMMA split-bf16 GEMM: C[m][n] = sum_k A[m][k]*B[n][k] (+bias[n])
// Output: fp32 (if C!=null) or bf16 hi/lo pair (Chi/Clo).
// CTA 128x128, BK=32, 256 threads (8 warps, 32m x 64n each), double-buffered.
// ---------------------------------------------------------------------------
#define GSTAGE 32768
#define GSMEM  (2 * GSTAGE)
#define NCHUNK 32

__device__ __forceinline__ void load_chunk(
    uint32_t sbase, int tid, int m0, int n0, int kc,
    const __nv_bfloat16* __restrict__ Ahi, const __nv_bfloat16* __restrict__ Alo,
    const __nv_bfloat16* __restrict__ Bhi, const __nv_bfloat16* __restrict__ Blo)
{
    const int row = tid >> 2;
    const int chunk = tid & 3;
    const int kcol = kc * 32 + chunk * 8;
#pragma unroll
    for (int u = 0; u < 2; u++) {
        const int r = row + u * 64;
        const uint32_t so = (uint32_t)(r * 64 + ((chunk ^ ((r >> 1) & 3)) << 4));
        CP16(sbase + so,         (const char*)(Ahi + (size_t)(m0 + r) * 1024 + kcol));
        CP16(sbase + 8192 + so,  (const char*)(Alo + (size_t)(m0 + r) * 1024 + kcol));
        CP16(sbase + 16384 + so, (const char*)(Bhi + (size_t)(n0 + r) * 1024 + kcol));
        CP16(sbase + 24576 + so, (const char*)(Blo + (size_t)(n0 + r) * 1024 + kcol));
    }
}

__global__ __launch_bounds__(256) void gemm_mma_kernel(
    const __nv_bfloat16* __restrict__ Ahi, const __nv_bfloat16* __restrict__ Alo,
    const __nv_bfloat16* __restrict__ Bhi, const __nv_bfloat16* __restrict__ Blo,
    const float* __restrict__ bias, float* __restrict__ C,
    __nv_bfloat16* __restrict__ Chi, __nv_bfloat16* __restrict__ Clo)
{
    extern __shared__ __align__(128) char smem[];
    const uint32_t sb = smem_u32(smem);
    const int tid = threadIdx.x;
    const int wid = tid >> 5;
    const int lid = tid & 31;
    const int n0 = blockIdx.x * 128;
    const int m0 = blockIdx.y * 128;
    const int warp_m = (wid >> 1) * 32;
    const int warp_n = (wid & 1) * 64;

    float acc[2][8][4];
#pragma unroll
    for (int a = 0; a < 2; a++)
#pragma unroll
        for (int b = 0; b < 8; b++)
#pragma unroll
            for (int c = 0; c < 4; c++) acc[a][b][c] = 0.f;

    load_chunk(sb, tid, m0, n0, 0, Ahi, Alo, Bhi, Blo);
    CP_COMMIT();

    const int sub = lid >> 3;
    const int r8  = lid & 7;

    for (int kc = 0; kc < NCHUNK; kc++) {
        const uint32_t cur = sb + (uint32_t)(kc & 1) * GSTAGE;
        if (kc + 1 < NCHUNK) {
            load_chunk(sb + (uint32_t)((kc + 1) & 1) * GSTAGE, tid, m0, n0, kc + 1,
                       Ahi, Alo, Bhi, Blo);
            CP_COMMIT();
            CP_WAIT(1);
        } else {
            CP_WAIT(0);
        }
        __syncthreads();

#pragma unroll
        for (int ks = 0; ks < 2; ks++) {
            const int kchunk = ks * 2 + (sub >> 1);
            uint32_t ahi[2][4], alo[2][4], bfr[4][4];
            uint32_t bad[4];
#pragma unroll
            for (int mt = 0; mt < 2; mt++) {
                const int mr = warp_m + mt * 16 + ((sub & 1) << 3) + r8;
                const uint32_t ad = cur + (uint32_t)(mr * 64 + ((kchunk ^ ((mr >> 1) & 3)) << 4));
                LDMX4(ahi[mt], ad);
                LDMX4(alo[mt], ad + 8192);
            }
#pragma unroll
            for (int nt = 0; nt < 4; nt++) {
                const int nr = warp_n + nt * 16 + ((sub & 1) << 3) + r8;
                bad[nt] = cur + 16384 + (uint32_t)(nr * 64 + ((kchunk ^ ((nr >> 1) & 3)) << 4));
                LDMX4(bfr[nt], bad[nt]);
            }
#pragma unroll
            for (int mt = 0; mt < 2; mt++)
#pragma unroll
                for (int nt = 0; nt < 4; nt++) {
                    MMA_BF16(acc[mt][2 * nt + 0], ahi[mt], bfr[nt][0], bfr[nt][2]);
                    MMA_BF16(acc[mt][2 * nt + 1], ahi[mt], bfr[nt][1], bfr[nt][3]);
                    MMA_BF16(acc[mt][2 * nt + 0], alo[mt], bfr[nt][0], bfr[nt][2]);
                    MMA_BF16(acc[mt][2 * nt + 1], alo[mt], bfr[nt][1], bfr[nt][3]);
                }
#pragma unroll
            for (int nt = 0; nt < 4; nt++)
                LDMX4(bfr[nt], bad[nt] + 8192);
#pragma unroll
            for (int mt = 0; mt < 2; mt++)
#pragma unroll
                for (int nt = 0; nt < 4; nt++) {
                    MMA_BF16(acc[mt][2 * nt + 0], ahi[mt], bfr[nt][0], bfr[nt][2]);
                    MMA_BF16(acc[mt][2 * nt + 1], ahi[mt], bfr[nt][1], bfr[nt][3]);
                }
        }
        __syncthreads();
    }

#pragma unroll
    for (int mt = 0; mt < 2; mt++) {
        const int mrow = m0 + warp_m + mt * 16 + (lid >> 2);
#pragma unroll
        for (int nt = 0; nt < 8; nt++) {
            const int ncol = n0 + warp_n + nt * 8 + 2 * (lid & 3);
            if (C) {
                float b0 = 0.f, b1 = 0.f;
                if (bias) { b0 = bias[ncol]; b1 = bias[ncol + 1]; }
                *(float2*)(C + (size_t)mrow * 1024 + ncol) =
                    make_float2(acc[mt][nt][0] + b0, acc[mt][nt][1] + b1);
                *(float2*)(C + (size_t)(mrow + 8) * 1024 + ncol) =
                    make_float2(acc[mt][nt][2] + b0, acc[mt][nt][3] + b1);
            } else {
                *(uint32_t*)(Chi + (size_t)mrow * 1024 + ncol) =
                    pack_bf2(acc[mt][nt][0], acc[mt][nt][1]);
                *(uint32_t*)(Clo + (size_t)mrow * 1024 + ncol) =
                    pack_bf2(bfres(acc[mt][nt][0]), bfres(acc[mt][nt][1]));
                *(uint32_t*)(Chi + (size_t)(mrow + 8) * 1024 + ncol) =
                    pack_bf2(acc[mt][nt][2], acc[mt][nt][3]);
                *(uint32_t*)(Clo + (size_t)(mrow + 8) * 1024 + ncol) =
                    pack_bf2(bfres(acc[mt][nt][2]), bfres(acc[mt][nt][3]));
            }
        }
    }
}

// ---------------------------------------------------------------------------
// Tensor-core flash attention (causal). CTA = 64 queries x 1 head, 128 thr
// (4 warps, each warp 16 q-rows). K-tiles of 64 keys, double-buffered cp.async.
// QK^T: 3-pass split bf16 (hh + hl + lh). PV: 3-pass (Phi*Vhi + Phi*Vlo + Plo*Vhi),
// P packed from S accumulators in registers. V consumed via ldmatrix.trans.
// Smem rows = 64 bf16 = 128B = 8 chunks of 16B, swizzle chunk ^= (row&7).
// ---------------------------------------------------------------------------
#define A_QHI 0
#define A_QLO 8192
#define A_ST  16384
#define A_STSZ 32768
#define A_KLO 8192
#define A_VHI 16384
#define A_VLO 24576
#define A_SMEM (A_ST + 2 * A_STSZ)   // 81920

__device__ __forceinline__ uint32_t aphys(int row, int chunk) {
    return (uint32_t)(row * 128 + (((chunk) ^ (row & 7)) << 4));
}

__device__ __forceinline__ void attn_load_kv(uint32_t st, int kb, int h, int tid) {
    const int r0 = tid >> 3;
    const int c  = tid & 7;
#pragma unroll
    for (int u = 0; u < 4; u++) {
        const int r = r0 + u * 16;
        const uint32_t so = aphys(r, c);
        const size_t gi = (size_t)(kb * 64 + r) * 1024 + h * 64 + c * 8;
        CP16(st + so,          (const char*)(g_khi + gi));
        CP16(st + A_KLO + so,  (const char*)(g_klo + gi));
        CP16(st + A_VHI + so,  (const char*)(g_vhi + gi));
        CP16(st + A_VLO + so,  (const char*)(g_vlo + gi));
    }
}

__global__ __launch_bounds__(128) void attn_kernel()
{
    extern __shared__ __align__(128) char smem[];
    const uint32_t sb = smem_u32(smem);
    const int tid = threadIdx.x;
    const int w = tid >> 5;
    const int l = tid & 31;
    const int qb = gridDim.x - 1 - blockIdx.x;   // long CTAs first
    const int h  = blockIdx.y;
    const int q0 = qb * 64;
    const int nkt = qb + 1;

    // Q tile load (hi+lo) -> group 0 together with K-tile 0
    {
        const int r0 = tid >> 3;
        const int c  = tid & 7;
#pragma unroll
        for (int u = 0; u < 4; u++) {
            const int r = r0 + u * 16;
            const uint32_t so = aphys(r, c);
            const size_t gi = (size_t)(q0 + r) * 1024 + h * 64 + c * 8;
            CP16(sb + A_QHI + so, (const char*)(g_qhi + gi));
            CP16(sb + A_QLO + so, (const char*)(g_qlo + gi));
        }
    }
    attn_load_kv(sb + A_ST, 0, h, tid);
    CP_COMMIT();

    uint32_t qfh[4][4], qfl[4][4];
    float O[8][4];
    float m0 = -INFINITY, m1 = -INFINITY, l0 = 0.f, l1 = 0.f;
#pragma unroll
    for (int nt = 0; nt < 8; nt++)
#pragma unroll
        for (int j = 0; j < 4; j++) O[nt][j] = 0.f;

    for (int kb = 0; kb < nkt; kb++) {
        if (kb + 1 < nkt) {
            attn_load_kv(sb + A_ST + (uint32_t)((kb + 1) & 1) * A_STSZ, kb + 1, h, tid);
            CP_COMMIT();
            CP_WAIT(1);
        } else {
            CP_WAIT(0);
        }
        __syncthreads();

        if (kb == 0) {
            const int row = 16 * w + (l & 15);
#pragma unroll
            for (int ks = 0; ks < 4; ks++) {
                const uint32_t ad = sb + A_QHI + aphys(row, 2 * ks + (l >> 4));
                LDMX4(qfh[ks], ad);
                LDMX4(qfl[ks], ad + 8192);
            }
        }

        const uint32_t st = sb + A_ST + (uint32_t)(kb & 1) * A_STSZ;

        // ---- S = Q K^T (3-pass) ----
        float s[8][4];
#pragma unroll
        for (int nt = 0; nt < 8; nt++)
#pragma unroll
            for (int j = 0; j < 4; j++) s[nt][j] = 0.f;

#pragma unroll
        for (int ks = 0; ks < 4; ks++) {
#pragma unroll
            for (int ntp = 0; ntp < 4; ntp++) {
                const int nrow = ntp * 16 + (l & 15);
                const uint32_t ad = st + aphys(nrow, 2 * ks + (l >> 4));
                uint32_t bh[4], bl[4];
                LDMX4(bh, ad);
                LDMX4(bl, ad + A_KLO);
                MMA_BF16(s[2 * ntp + 0], qfh[ks], bh[0], bh[2]);
                MMA_BF16(s[2 * ntp + 1], qfh[ks], bh[1], bh[3]);
                MMA_BF16(s[2 * ntp + 0], qfl[ks], bh[0], bh[2]);
                MMA_BF16(s[2 * ntp + 1], qfl[ks], bh[1], bh[3]);
                MMA_BF16(s[2 * ntp + 0], qfh[ks], bl[0], bl[2]);
                MMA_BF16(s[2 * ntp + 1], qfh[ks], bl[1], bl[3]);
            }
        }

        // ---- scale + causal mask ----
        if (kb == qb) {
            const int rl0 = 16 * w + (l >> 2);
#pragma unroll
            for (int nt = 0; nt < 8; nt++) {
                const int c0 = nt * 8 + 2 * (l & 3);
                s[nt][0] = (c0     > rl0    ) ? -INFINITY : s[nt][0] * 0.125f;
                s[nt][1] = (c0 + 1 > rl0    ) ? -INFINITY : s[nt][1] * 0.125f;
                s[nt][2] = (c0     > rl0 + 8) ? -INFINITY : s[nt][2] * 0.125f;
                s[nt][3] = (c0 + 1 > rl0 + 8) ? -INFINITY : s[nt][3] * 0.125f;
            }
        } else {
#pragma unroll
            for (int nt = 0; nt < 8; nt++)
#pragma unroll
                for (int j = 0; j < 4; j++) s[nt][j] *= 0.125f;
        }

        // ---- online softmax (rows r = l>>2 and r+8) ----
        float mr0 = -INFINITY, mr1 = -INFINITY;
#pragma unroll
        for (int nt = 0; nt < 8; nt++) {
            mr0 = fmaxf(mr0, fmaxf(s[nt][0], s[nt][1]));
            mr1 = fmaxf(mr1, fmaxf(s[nt][2], s[nt][3]));
        }
        mr0 = fmaxf(mr0, __shfl_xor_sync(0xffffffffu, mr0, 1));
        mr0 = fmaxf(mr0, __shfl_xor_sync(0xffffffffu, mr0, 2));
        mr1 = fmaxf(mr1, __shfl_xor_sync(0xffffffffu, mr1, 1));
        mr1 = fmaxf(mr1, __shfl_xor_sync(0xffffffffu, mr1, 2));
        const float mn0 = fmaxf(m0, mr0);
        const float mn1 = fmaxf(m1, mr1);
        const float a0 = __expf(m0 - mn0);
        const float a1 = __expf(m1 - mn1);

        float sum0 = 0.f, sum1 = 0.f;
#pragma unroll
        for (int nt = 0; nt < 8; nt++) {
            s[nt][0] = __expf(s[nt][0] - mn0); sum0 += s[nt][0];
            s[nt][1] = __expf(s[nt][1] - mn0); sum0 += s[nt][1];
            s[nt][2] = __expf(s[nt][2] - mn1); sum1 += s[nt][2];
            s[nt][3] = __expf(s[nt][3] - mn1); sum1 += s[nt][3];
        }
        sum0 += __shfl_xor_sync(0xffffffffu, sum0, 1);
        sum0 += __shfl_xor_sync(0xffffffffu, sum0, 2);
        sum1 += __shfl_xor_sync(0xffffffffu, sum1, 1);
        sum1 += __shfl_xor_sync(0xffffffffu, sum1, 2);
        l0 = l0 * a0 + sum0;
        l1 = l1 * a1 + sum1;
        m0 = mn0; m1 = mn1;

#pragma unroll
        for (int nt = 0; nt < 8; nt++) {
            O[nt][0] *= a0; O[nt][1] *= a0;
            O[nt][2] *= a1; O[nt][3] *= a1;
        }

        // ---- O += P V (3-pass), P packed from registers ----
#pragma unroll
        for (int ks = 0; ks < 4; ks++) {
            uint32_t ph[4], pl[4];
            ph[0] = pack_bf2(s[2 * ks][0],     s[2 * ks][1]);
            ph[1] = pack_bf2(s[2 * ks][2],     s[2 * ks][3]);
            ph[2] = pack_bf2(s[2 * ks + 1][0], s[2 * ks + 1][1]);
            ph[3] = pack_bf2(s[2 * ks + 1][2], s[2 * ks + 1][3]);
            pl[0] = pack_bf2(bfres(s[2 * ks][0]),     bfres(s[2 * ks][1]));
            pl[1] = pack_bf2(bfres(s[2 * ks][2]),     bfres(s[2 * ks][3]));
            pl[2] = pack_bf2(bfres(s[2 * ks + 1][0]), bfres(s[2 * ks + 1][1]));
            pl[3] = pack_bf2(bfres(s[2 * ks + 1][2]), bfres(s[2 * ks + 1][3]));
            const int vrow = 16 * ks + (l & 15);
#pragma unroll
            for (int dtp = 0; dtp < 4; dtp++) {
                const uint32_t ad = st + A_VHI + aphys(vrow, 2 * dtp + (l >> 4));
                uint32_t vh[4], vl[4];
                LDMX4T(vh, ad);
                LDMX4T(vl, ad + 8192);
                MMA_BF16(O[2 * dtp + 0], ph, vh[0], vh[1]);
                MMA_BF16(O[2 * dtp + 1], ph, vh[2], vh[3]);
                MMA_BF16(O[2 * dtp + 0], pl, vh[0], vh[1]);
                MMA_BF16(O[2 * dtp + 1], pl, vh[2], vh[3]);
                MMA_BF16(O[2 * dtp + 0], ph, vl[0], vl[1]);
                MMA_BF16(O[2 * dtp + 1], ph, vl[2], vl[3]);
            }
        }
        __syncthreads();
    }

    // ---- epilogue: ctx hi/lo bf16 ----
    const float i0 = 1.f / l0;
    const float i1 = 1.f / l1;
    const int rg0 = q0 + 16 * w + (l >> 2);
    const int cb = h * 64 + 2 * (l & 3);
#pragma unroll
    for (int nt = 0; nt < 8; nt++) {
        const float v00 = O[nt][0] * i0, v01 = O[nt][1] * i0;
        const float v10 = O[nt][2] * i1, v11 = O[nt][3] * i1;
        const size_t o0 = (size_t)rg0 * 1024 + cb + nt * 8;
        const size_t o1 = (size_t)(rg0 + 8) * 1024 + cb + nt * 8;
        *(uint32_t*)(g_chi + o0) = pack_bf2(v00, v01);
        *(uint32_t*)(g_clo + o0) = pack_bf2(bfres(v00), bfres(v01));
        *(uint32_t*)(g_chi + o1) = pack_bf2(v10, v11);
        *(uint32_t*)(g_clo + o1) = pack_bf2(bfres(v10), bfres(v11));
    }
}

// ---------------------------------------------------------------------------
extern "C" void kernel_launch(void* const* d_in, const int* in_sizes, int n_in,
                              void* d_out, int out_size)
{
    const float* x  = (const float*)d_in[0];
    const float* Wq = (const float*)d_in[1];
    const float* Wk = (const float*)d_in[2];
    const float* Wv = (const float*)d_in[3];
    const float* Wo = (const float*)d_in[4];
    const float* bo = (const float*)d_in[5];
    float* out = (float*)d_out;

    __nv_bfloat16 *xhi, *xlo, *whi, *wlo;
    __nv_bfloat16 *qhi, *qlo, *khi, *klo, *vhi, *vlo, *chi, *clo;
    cudaGetSymbolAddress((void**)&xhi, g_xhi);
    cudaGetSymbolAddress((void**)&xlo, g_xlo);
    cudaGetSymbolAddress((void**)&whi, g_whi);
    cudaGetSymbolAddress((void**)&wlo, g_wlo);
    cudaGetSymbolAddress((void**)&qhi, g_qhi);
    cudaGetSymbolAddress((void**)&qlo, g_qlo);
    cudaGetSymbolAddress((void**)&khi, g_khi);
    cudaGetSymbolAddress((void**)&klo, g_klo);
    cudaGetSymbolAddress((void**)&vhi, g_vhi);
    cudaGetSymbolAddress((void**)&vlo, g_vlo);
    cudaGetSymbolAddress((void**)&chi, g_chi);
    cudaGetSymbolAddress((void**)&clo, g_clo);

    const int NX = N_TOK * D_MODEL;       // 4M
    const int NW = D_MODEL * D_MODEL;     // 1M
    const float* Ws[4] = {Wq, Wk, Wv, Wo};

    split_kernel<<<NX / 1024, 256>>>(x, xhi, xlo, NX);
    for (int i = 0; i < 4; i++)
        split_kernel<<<NW / 1024, 256>>>(Ws[i], whi + (size_t)i * NW, wlo + (size_t)i * NW, NW);

    cudaFuncSetAttribute(gemm_mma_kernel, cudaFuncAttributeMaxDynamicSharedMemorySize, GSMEM);
    dim3 gg(D_MODEL / 128, N_TOK / 128);  // (8, 32)

    gemm_mma_kernel<<<gg, 256, GSMEM>>>(xhi, xlo, whi + 0 * (size_t)NW, wlo + 0 * (size_t)NW,
                                        nullptr, nullptr, qhi, qlo);
    gemm_mma_kernel<<<gg, 256, GSMEM>>>(xhi, xlo, whi + 1 * (size_t)NW, wlo + 1 * (size_t)NW,
                                        nullptr, nullptr, khi, klo);
    gemm_mma_kernel<<<gg, 256, GSMEM>>>(xhi, xlo, whi + 2 * (size_t)NW, wlo + 2 * (size_t)NW,
                                        nullptr, nullptr, vhi, vlo);

    cudaFuncSetAttribute(attn_kernel, cudaFuncAttributeMaxDynamicSharedMemorySize, A_SMEM);
    attn_kernel<<<dim3(N_TOK / 64, N_HEADS), 128, A_SMEM>>>();

    gemm_mma_kernel<<<gg, 256, GSMEM>>>(chi, clo, whi + 3 * (size_t)NW, wlo + 3 * (size_t)NW,
                                        bo, out, nullptr, nullptr);
}